// round 16
// baseline (speedup 1.0000x reference)
#include <cuda_runtime.h>
#include <cuda_fp16.h>
#include <cstdint>
#include <cstddef>

#define Bsz 16
#define H4 28
#define W4 64
#define HW (H4*W4)
#define C1 96
#define FEATC 631
#define FEATB (FEATC*HW)
#define FULL_H 448
#define FULL_W 1024
#define NWORD 320
#define NS 8

__device__ float gRv[(size_t)Bsz*2*H4*FULL_W];
__device__ float gW1[(size_t)Bsz*C1*HW];
__device__ float gW2[(size_t)Bsz*C1*HW];
__device__ unsigned gActHi[(size_t)Bsz*NWORD*HW];
__device__ unsigned gWpHi[884736];
__device__ float gDF[(size_t)NS*Bsz*2*HW];

__device__ __forceinline__ float lrelu(float v){ return v >= 0.f ? v : 0.1f*v; }
__device__ __forceinline__ unsigned packh2(float a, float b){
    __half h0 = __float2half_rn(a), h1 = __float2half_rn(b);
    return ((unsigned)__half_as_ushort(h1) << 16) | (unsigned)__half_as_ushort(h0);
}

// ============ fused prep: resizeVf | copyone | deconv_flow | dfeat | wpack×5
__global__ void __launch_bounds__(256) k_prep(
    const float* __restrict__ quat, const float* __restrict__ K, const float* __restrict__ Kinv,
    const float* __restrict__ tenOne,
    const float* __restrict__ prev_flow, const float* __restrict__ upflow_w, const float* __restrict__ upflow_b,
    const float* __restrict__ prev_feat, const float* __restrict__ upfeat_w,
    const float* __restrict__ w1, const float* __restrict__ w2, const float* __restrict__ w3,
    const float* __restrict__ w4, const float* __restrict__ w5,
    float* __restrict__ feat)
{
    __shared__ float sh[1936];
    const int blk = blockIdx.x;
    const int tid = threadIdx.x;

    if (blk < 1792){
        int idx = blk*256 + tid;
        int x = idx % FULL_W;
        int i = (idx / FULL_W) % H4;
        int b = idx / (FULL_W*H4);
        float* M = &sh[1920];
        if (tid == 0){
            float q0=quat[b*4+0], q1=quat[b*4+1], q2=quat[b*4+2], q3=quat[b*4+3];
            float n = sqrtf(q0*q0+q1*q1+q2*q2+q3*q3);
            float w=q0/n, xr=q1/n, yr=q2/n, zr=q3/n;
            float R[9];
            R[0]=1.f-2.f*(yr*yr+zr*zr); R[1]=2.f*(xr*yr-w*zr);      R[2]=2.f*(xr*zr+w*yr);
            R[3]=2.f*(xr*yr+w*zr);      R[4]=1.f-2.f*(xr*xr+zr*zr); R[5]=2.f*(yr*zr-w*xr);
            R[6]=2.f*(xr*zr-w*yr);      R[7]=2.f*(yr*zr+w*xr);      R[8]=1.f-2.f*(xr*xr+yr*yr);
            float T[9];
            for (int ii=0;ii<3;ii++) for (int jj=0;jj<3;jj++){
                float s=0.f; for (int k=0;k<3;k++) s += K[ii*3+k]*R[k*3+jj]; T[ii*3+jj]=s;
            }
            for (int ii=0;ii<3;ii++) for (int jj=0;jj<3;jj++){
                float s=0.f; for (int k=0;k<3;k++) s += T[ii*3+k]*Kinv[k*3+jj]; M[ii*3+jj]=s;
            }
        }
        __syncthreads();
        float M1=M[1],M4=M[4],M7=M[7];
        float fx = (float)x;
        float ux = M[0]*fx + M[2], vx = M[3]*fx + M[5], wxc = M[6]*fx + M[8];
        float pos = 16.0f*i + 7.5f;
        int ys = 16*i - 8;
        int yA = ys < 0 ? 0 : ys;
        int yB = (ys+31 > FULL_H-1) ? (FULL_H-1) : (ys+31);
        float a0=0.f, a1=0.f, ws=0.f;
        float w = wxc + M7*(float)yA;
        float r = 1.0f / w;
        for (int yy=yA; yy<=yB; yy++){
            float fy = (float)yy;
            r = r*(2.0f - w*r);
            float wgt = 1.0f - fabsf(fy - pos) * 0.0625f;
            a0 += wgt * ((ux + M1*fy)*r - fx);
            a1 += wgt * ((vx + M4*fy)*r - fy);
            ws += wgt;
            w += M7;
        }
        float rws = 1.0f / ws;
        size_t o = ((size_t)(b*2)*H4 + i)*FULL_W + x;
        gRv[o]                     = a0*rws;
        gRv[o + (size_t)H4*FULL_W] = a1*rws;
    }
    else if (blk < 12544){
        int idx = (blk-1792)*256 + tid;
        int p = idx % HW;
        int c = (idx / HW) % C1;
        int b = idx / (HW*C1);
        feat[(size_t)b*FEATB + (size_t)(531+c)*HW + p] = tenOne[idx];
    }
    else if (blk < 12768){
        int idx = (blk-12544)*256 + tid;
        int x = idx % W4;
        int y = (idx / W4) % H4;
        int o = (idx / HW) % 2;
        int b = idx / (2*HW);
        float acc = upflow_b[o];
        for (int t=0;t<2;t++){
            int ky = (y & 1) + 2*t;
            int iy = (y + ky - 2) / 2;
            if ((y + ky - 2) < 0 || iy >= 14) continue;
            for (int s=0;s<2;s++){
                int kx = (x & 1) + 2*s;
                int ix = (x + kx - 2) / 2;
                if ((x + kx - 2) < 0 || ix >= 32) continue;
                for (int c=0;c<2;c++)
                    acc += prev_flow[((b*2 + c)*14 + iy)*32 + ix] * upflow_w[((c*2 + o)*4 + (3-ky))*4 + (3-kx)];
            }
        }
        feat[(size_t)b*FEATB + (size_t)(627+o)*HW + y*W4 + x] = acc;
    }
    else if (blk < 12896){
        int local = blk - 12768;
        int b = local & 15, sp = local >> 4;
        int cs = (663*sp)/NS, ce = (663*(sp+1))/NS;
        int x = tid & 63;
        int ybase = tid >> 6;
        float* sd  = sh;
        float* swt = sh + 1792;
        int ixs[2], wbs[2], nkx=0;
        for (int t=0;t<2;t++){
            int kx=(x&1)+2*t, num=x+kx-2, ix=num/2;
            if (num>=0 && ix<32){ ixs[nkx]=ix; wbs[nkx]=3-kx; nkx++; }
        }
        int p = ybase & 1;
        int wrow[2] = {3-p, 1-p};
        int iyk[7][2]; unsigned vmask[7];
        #pragma unroll
        for (int k=0;k<7;k++){
            int y = ybase + 4*k;
            vmask[k]=0;
            #pragma unroll
            for (int t=0;t<2;t++){
                int ky=(y&1)+2*t, num=y+ky-2, iy=num/2;
                if (num>=0 && iy<14) vmask[k] |= (1u<<t);
                iyk[k][t] = (iy<0)?0:((iy>13)?13:iy);
            }
        }
        float acc0[7], acc1[7];
        #pragma unroll
        for (int k=0;k<7;k++){ acc0[k]=0.f; acc1[k]=0.f; }

        for (int c=cs; c<ce; c+=4){
            __syncthreads();
            for (int i=tid; i<4*448; i+=256){
                int k = i / 448, j = i % 448;
                sd[k*448+j] = (c+k < ce) ? prev_feat[((size_t)b*663 + c+k)*448 + j] : 0.f;
            }
            if (tid < 128){
                int k = tid >> 5, j = tid & 31;
                swt[k*32+j] = (c+k < ce) ? upfeat_w[(size_t)(c+k)*32 + j] : 0.f;
            }
            __syncthreads();
            #pragma unroll
            for (int cc=0; cc<4; cc++){
                float wr[2][2][2];
                #pragma unroll
                for (int t=0;t<2;t++)
                    for (int j=0;j<2;j++){
                        int wc = (j<nkx)? wbs[j] : 0;
                        wr[0][t][j] = (j<nkx)? swt[cc*32 + wrow[t]*4 + wc]      : 0.f;
                        wr[1][t][j] = (j<nkx)? swt[cc*32 + 16 + wrow[t]*4 + wc] : 0.f;
                    }
                #pragma unroll
                for (int k=0;k<7;k++){
                    #pragma unroll
                    for (int t=0;t<2;t++){
                        if (!(vmask[k]>>t & 1)) continue;
                        const float* row = &sd[cc*448 + iyk[k][t]*32];
                        #pragma unroll
                        for (int j=0;j<2;j++){
                            if (j>=nkx) break;
                            float v = row[ixs[j]];
                            acc0[k] += v*wr[0][t][j];
                            acc1[k] += v*wr[1][t][j];
                        }
                    }
                }
            }
        }
        size_t base = ((size_t)(sp*Bsz + b)*2)*HW;
        #pragma unroll
        for (int k=0;k<7;k++){
            int y = ybase + 4*k;
            gDF[base + y*W4 + x]      = acc0[k];
            gDF[base + HW + y*W4 + x] = acc1[k];
        }
    }
    else {
        int wb = blk - 12896;
        const float* w; int cin, cout, coutp, off, idx;
        if (wb < 432)      { w=w1; cin=183; cout=128; coutp=128; off=0;      idx = wb*256 + tid; }
        else if (wb < 1152){ w=w2; cin=311; cout=128; coutp=128; off=110592; idx = (wb-432)*256 + tid; }
        else if (wb < 2160){ w=w3; cin=439; cout= 96; coutp=128; off=294912; idx = (wb-1152)*256 + tid; }
        else if (wb < 2772){ w=w4; cin=535; cout= 64; coutp= 64; off=552960; idx = (wb-2160)*256 + tid; }
        else               { w=w5; cin=599; cout= 32; coutp= 64; off=709632; idx = (wb-2772)*256 + tid; }
        int n    = idx % coutp;
        int w8   = (idx / coutp) % 8;
        int tap  = (idx / (coutp*8)) % 9;
        int chunk= idx / (coutp*72);
        int c0 = 2*(chunk*8 + w8), c1 = c0 + 1;
        float v0 = (n < cout && c0 < cin) ? w[((size_t)n*cin + c0)*9 + tap] : 0.f;
        float v1 = (n < cout && c1 < cin) ? w[((size_t)n*cin + c1)*9 + tap] : 0.f;
        gWpHi[off + idx] = packh2(v0, v1);
    }
}

// ============ fused prep2: resizeH | dfred
__global__ void __launch_bounds__(256) k_prep2(const float* __restrict__ upfeat_b, float* __restrict__ feat){
    const int blk = blockIdx.x;
    const int tid = threadIdx.x;
    if (blk < 112){
        int idx = blk*256 + tid;
        int j = idx % W4;
        int i = (idx / W4) % H4;
        int b = idx / HW;
        float pos = 16.0f*j + 7.5f;
        int xs = 16*j - 8;
        float a0=0.f, a1=0.f, ws=0.f;
        const float* p0 = &gRv[((size_t)(b*2)*H4 + i)*FULL_W];
        const float* p1 = p0 + (size_t)H4*FULL_W;
        for (int t=0;t<32;t++){
            int xx = xs + t;
            if (xx < 0 || xx >= FULL_W) continue;
            float wgt = 1.0f - fabsf((float)xx - pos) * 0.0625f;
            a0 += wgt * p0[xx];
            a1 += wgt * p1[xx];
            ws += wgt;
        }
        float rws = 1.0f / ws;
        size_t o = (size_t)b*FEATB + (size_t)529*HW + i*W4 + j;
        feat[o]      = (a0*rws)*0.0625f;
        feat[o + HW] = (a1*rws)*0.0625f;
    } else {
        int idx = (blk-112)*256 + tid;
        int pq = idx % HW;
        int o  = (idx / HW) & 1;
        int b  = idx / (2*HW);
        float s = upfeat_b[o];
        for (int sp=0; sp<NS; sp++)
            s += gDF[((size_t)(sp*Bsz + b)*2 + o)*HW + pq];
        feat[(size_t)b*FEATB + (size_t)(629+o)*HW + pq] = s;
    }
}

// ============ bilinear warps (12-way channel-split)
__device__ __forceinline__ void warp_px(const float* __restrict__ srcB, float* __restrict__ dstB,
                                        float fx, float fy, int x, int y, int c0, int c1){
    float xx = (float)x + fx, yy = (float)y + fy;
    float x0 = floorf(xx), y0 = floorf(yy);
    float wx = xx - x0, wy = yy - y0;
    float ys2[2] = { y0, y0 + 1.f };
    float xs2[2] = { x0, x0 + 1.f };
    float wyv[2] = { 1.f - wy, wy };
    float wxv[2] = { 1.f - wx, wx };
    float wgt[4]; int off[4];
    #pragma unroll
    for (int i=0;i<2;i++)
        #pragma unroll
        for (int j=0;j<2;j++){
            bool valid = (ys2[i] >= 0.f) && (ys2[i] <= (float)(H4-1)) && (xs2[j] >= 0.f) && (xs2[j] <= (float)(W4-1));
            float yc = fminf(fmaxf(ys2[i], 0.f), (float)(H4-1));
            float xc = fminf(fmaxf(xs2[j], 0.f), (float)(W4-1));
            off[i*2+j] = (int)yc * W4 + (int)xc;
            wgt[i*2+j] = valid ? (wyv[i]*wxv[j]) : 0.f;
        }
    int obase = y*W4 + x;
    #pragma unroll
    for (int c=c0;c<c1;c++){
        const float* s = srcB + (size_t)c*HW;
        dstB[(size_t)c*HW + obase] = wgt[0]*s[off[0]] + wgt[1]*s[off[1]] + wgt[2]*s[off[2]] + wgt[3]*s[off[3]];
    }
}

__global__ void k_warp1(const float* __restrict__ tenTwo, const float* __restrict__ feat){
    int idx = blockIdx.x*blockDim.x + threadIdx.x;
    if (idx >= Bsz*HW) return;
    int cg = blockIdx.y;
    int x = idx % W4, y = (idx / W4) % H4, b = idx / HW;
    const float* fp = feat + (size_t)b*FEATB + (size_t)529*HW + y*W4 + x;
    warp_px(tenTwo + (size_t)b*C1*HW, gW1 + (size_t)b*C1*HW, fp[0], fp[HW], x, y, cg*8, cg*8+8);
}
__global__ void k_warp2(const float* __restrict__ feat){
    int idx = blockIdx.x*blockDim.x + threadIdx.x;
    if (idx >= Bsz*HW) return;
    int cg = blockIdx.y;
    int x = idx % W4, y = (idx / W4) % H4, b = idx / HW;
    const float* fp = feat + (size_t)b*FEATB + (size_t)627*HW + y*W4 + x;
    warp_px(gW1 + (size_t)b*C1*HW, gW2 + (size_t)b*C1*HW, fp[0]*1.25f, fp[HW]*1.25f, x, y, cg*8, cg*8+8);
}

// ============ correlation + packed fp16 act words 224..319
__global__ void __launch_bounds__(256) k_corr(const float* __restrict__ one, float* __restrict__ feat){
    __shared__ float s1[8][4][64];
    __shared__ float s2[8][12][72];
    int tid = threadIdx.x;
    int tx = tid % 64, tyl = tid / 64;
    int b = blockIdx.y, rt = blockIdx.x;
    int y = rt*4 + tyl;
    float acc[81];
    #pragma unroll
    for (int d=0; d<81; d++) acc[d] = 0.f;
    const float* oneB = one + (size_t)b*C1*HW;
    const float* twoB = gW2 + (size_t)b*C1*HW;
    for (int c0=0; c0<C1; c0+=8){
        __syncthreads();
        for (int i=tid; i<8*4*64; i+=256){
            int c = i / 256; int r = (i / 64) % 4; int xx = i % 64;
            s1[c][r][xx] = oneB[(size_t)(c0+c)*HW + (rt*4+r)*64 + xx];
        }
        for (int i=tid; i<8*12*72; i+=256){
            int c = i / (12*72); int rem = i % (12*72);
            int r = rem / 72; int xx = rem % 72;
            int gy = rt*4 + r - 4, gx = xx - 4;
            float v = 0.f;
            if (gy >= 0 && gy < H4 && gx >= 0 && gx < W4) v = twoB[(size_t)(c0+c)*HW + gy*64 + gx];
            s2[c][r][xx] = v;
        }
        __syncthreads();
        #pragma unroll
        for (int c=0;c<8;c++){
            float f1 = s1[c][tyl][tx];
            #pragma unroll
            for (int dy=0;dy<9;dy++){
                const float* row = &s2[c][tyl+dy][tx];
                #pragma unroll
                for (int dx=0;dx<9;dx++) acc[dy*9+dx] += f1 * row[dx];
            }
        }
    }
    float* fb = feat + (size_t)b*FEATB + (size_t)448*HW + y*64 + tx;
    const float inv = 1.0f/96.0f;
    #pragma unroll
    for (int d=0; d<81; d++){
        acc[d] = lrelu(acc[d]*inv);
        fb[(size_t)d*HW] = acc[d];
    }
    int pix = y*64 + tx;
    unsigned* oh = gActHi + ((size_t)b*NWORD + 224)*HW + pix;
    #pragma unroll
    for (int k=0;k<40;k++)
        oh[(size_t)k*HW] = packh2(acc[2*k], acc[2*k+1]);
    const float* fb2 = feat + (size_t)b*FEATB;
    unsigned* oh2 = gActHi + ((size_t)b*NWORD + 264)*HW + pix;
    for (int k=0;k<56;k++){
        int c0 = 528 + 2*k, c1 = c0 + 1;
        float v0 = (k==0) ? acc[80] : ((c0 < FEATC) ? fb2[(size_t)c0*HW + pix] : 0.f);
        float v1 = (c1 < FEATC) ? fb2[(size_t)c1*HW + pix] : 0.f;
        oh2[(size_t)k*HW] = packh2(v0, v1);
    }
}

#define MMA16816(d, a, b) \
    asm volatile("mma.sync.aligned.m16n8k16.row.col.f32.f16.f16.f32 " \
        "{%0,%1,%2,%3}, {%4,%5,%6,%7}, {%8,%9}, {%0,%1,%2,%3};" \
        : "+f"(d[0]), "+f"(d[1]), "+f"(d[2]), "+f"(d[3]) \
        : "r"(a[0]), "r"(a[1]), "r"(a[2]), "r"(a[3]), "r"(b[0]), "r"(b[1]))

__device__ __forceinline__ void cpa16(unsigned dst, const void* src){
    asm volatile("cp.async.ca.shared.global [%0], [%1], 16;" :: "r"(dst), "l"(src));
}

#define ABUF 3648
#define BBUF 2880
#define SMEMW (2*ABUF + 2*BBUF)
#define SMEM_GEMM (SMEMW*4)

__global__ void __launch_bounds__(256,3) k_gemm(const float* __restrict__ bias, float* __restrict__ feat,
    int cs_word, int chunks, int coutp, int cout, int obase_ch, int wp_off)
{
    extern __shared__ unsigned sm[];
    unsigned* sAh = sm;
    unsigned* sBh = sm + 2*ABUF;
    const unsigned sbase = (unsigned)__cvta_generic_to_shared(sm);

    const int tile = blockIdx.x;
    const int ng = blockIdx.y;
    const int b = tile / 7;
    const int y0 = (tile % 7) * 4;
    const int tid = threadIdx.x;
    const int lane = tid & 31, warp = tid >> 5;
    const int row_w = warp >> 1;
    const int xb = (warp & 1) * 32;
    const int r4 = lane >> 2, w4 = lane & 3;

    for (int i=tid; i<SMEMW; i+=256) sm[i] = 0u;
    __syncthreads();

    const unsigned* gh = gActHi + (size_t)b*NWORD*HW;

    float acc[2][4][4];
    #pragma unroll
    for (int m=0;m<2;m++)
        #pragma unroll
        for (int n=0;n<4;n++){ acc[m][n][0]=0.f; acc[m][n][1]=0.f; acc[m][n][2]=0.f; acc[m][n][3]=0.f; }

    auto load_chunk = [&](int ch, int bf){
        int cw0 = cs_word + ch*8;
        #pragma unroll
        for (int it=0; it<3; it++){
            int i = it*256 + tid;
            int q = i & 15;
            int j = i >> 4;
            int r = j % 6;
            int w = j / 6;
            int gy = y0 - 1 + r;
            if (gy >= 0 && gy < H4){
                const unsigned* src = gh + (size_t)(cw0+w)*HW + gy*W4 + q*4;
                unsigned dst = sbase + (bf*ABUF + (w*6+r)*76 + 4 + q*4)*4;
                cpa16(dst, src);
            }
        }
        for (int i=tid; i<576; i+=256){
            int q = i & 7;
            int tw = i >> 3;
            const unsigned* src = gWpHi + wp_off + (size_t)(ch*72 + tw)*coutp + ng*32 + q*4;
            unsigned dst = sbase + (2*ABUF + bf*BBUF + tw*40 + q*4)*4;
            cpa16(dst, src);
        }
    };

    load_chunk(0, 0);
    asm volatile("cp.async.commit_group;");
    int buf = 0;
    for (int ch=0; ch<chunks; ch++){
        if (ch+1 < chunks) load_chunk(ch+1, buf^1);
        asm volatile("cp.async.commit_group;");
        asm volatile("cp.async.wait_group 1;");
        __syncthreads();

        const unsigned* Ah = sAh + buf*ABUF;
        const unsigned* Bh = sBh + buf*BBUF;
        #pragma unroll
        for (int tap=0; tap<9; tap++){
            int ky = tap/3, kx = tap%3;
            unsigned ah[2][4], bh[4][2];
            #pragma unroll
            for (int m=0;m<2;m++){
                int base = (w4*6 + row_w + ky)*76 + 3 + kx + xb + m*16 + r4;
                ah[m][0]=Ah[base]; ah[m][1]=Ah[base+8]; ah[m][2]=Ah[base+1824]; ah[m][3]=Ah[base+1832];
            }
            #pragma unroll
            for (int n=0;n<4;n++){
                int bidx = (tap*8 + w4)*40 + n*8 + r4;
                bh[n][0]=Bh[bidx]; bh[n][1]=Bh[bidx+160];
            }
            #pragma unroll
            for (int m=0;m<2;m++)
                #pragma unroll
                for (int n=0;n<4;n++)
                    MMA16816(acc[m][n], ah[m], bh[n]);
        }
        __syncthreads();
        buf ^= 1;
    }

    float* fb = feat + (size_t)b*FEATB;
    unsigned* oh = gActHi + (size_t)b*NWORD*HW;
    int y = y0 + row_w;
    #pragma unroll
    for (int m=0;m<2;m++){
        int xp = xb + m*16 + r4;
        #pragma unroll
        for (int n=0;n<4;n++){
            int chl = ng*32 + n*8 + 2*w4;
            if (chl < cout){
                float b0 = bias[chl], b1 = bias[chl+1];
                #pragma unroll
                for (int h=0; h<2; h++){
                    float v0 = lrelu(acc[m][n][2*h+0] + b0);
                    float v1 = lrelu(acc[m][n][2*h+1] + b1);
                    int xx = xp + h*8;
                    size_t o = (size_t)(obase_ch + chl)*HW + y*W4 + xx;
                    fb[o]      = v0;
                    fb[o + HW] = v1;
                    oh[(size_t)((obase_ch + chl) >> 1)*HW + y*W4 + xx] = packh2(v0, v1);
                }
            }
        }
    }
}

// ============ 2-row-tile gemm, A layout [row][word] stride 76 (16B-aligned cp.async)
#define ABUF2 (4*8*76)   // 2432
#define SMEMW2 (2*ABUF2 + 2*BBUF)
#define SMEM_GEMM2 (SMEMW2*4)

__global__ void __launch_bounds__(256,4) k_gemm2(const float* __restrict__ bias, float* __restrict__ feat,
    int cs_word, int chunks, int coutp, int cout, int obase_ch, int wp_off)
{
    extern __shared__ unsigned sm[];
    unsigned* sAh = sm;
    unsigned* sBh = sm + 2*ABUF2;
    const unsigned sbase = (unsigned)__cvta_generic_to_shared(sm);

    const int tile = blockIdx.x;          // 0..223
    const int ng = blockIdx.y;
    const int b = tile / 14;
    const int y0 = (tile % 14) * 2;
    const int tid = threadIdx.x;
    const int lane = tid & 31, warp = tid >> 5;
    const int row_w = warp >> 2;          // 2 rows
    const int xbh = (warp >> 1) & 1;      // 2 x-halves
    const int mp = warp & 1;              // 2 m16 sub-tiles
    const int r4 = lane >> 2, w4 = lane & 3;

    for (int i=tid; i<SMEMW2; i+=256) sm[i] = 0u;
    __syncthreads();

    const unsigned* gh = gActHi + (size_t)b*NWORD*HW;

    float acc[4][4];
    #pragma unroll
    for (int n=0;n<4;n++){ acc[n][0]=0.f; acc[n][1]=0.f; acc[n][2]=0.f; acc[n][3]=0.f; }

    auto load_chunk = [&](int ch, int bf){
        int cw0 = cs_word + ch*8;
        // A: 8 words * 4 rows * 16 quads = 512 items; layout [row][word], stride 76
        #pragma unroll
        for (int it=0; it<2; it++){
            int i = it*256 + tid;
            int q = i & 15;
            int j = i >> 4;        // 0..31
            int r = j & 3;
            int w = j >> 2;
            int gy = y0 - 1 + r;
            if (gy >= 0 && gy < H4){
                const unsigned* src = gh + (size_t)(cw0+w)*HW + gy*W4 + q*4;
                unsigned dst = sbase + (bf*ABUF2 + (r*8+w)*76 + 4 + q*4)*4;
                cpa16(dst, src);
            }
        }
        for (int i=tid; i<576; i+=256){
            int q = i & 7;
            int tw = i >> 3;
            const unsigned* src = gWpHi + wp_off + (size_t)(ch*72 + tw)*coutp + ng*32 + q*4;
            unsigned dst = sbase + (2*ABUF2 + bf*BBUF + tw*40 + q*4)*4;
            cpa16(dst, src);
        }
    };

    load_chunk(0, 0);
    asm volatile("cp.async.commit_group;");
    int buf = 0;
    for (int ch=0; ch<chunks; ch++){
        if (ch+1 < chunks) load_chunk(ch+1, buf^1);
        asm volatile("cp.async.commit_group;");
        asm volatile("cp.async.wait_group 1;");
        __syncthreads();

        const unsigned* Ah = sAh + buf*ABUF2;
        const unsigned* Bh = sBh + buf*BBUF;
        #pragma unroll
        for (int tap=0; tap<9; tap++){
            int ky = tap/3, kx = tap%3;
            unsigned ah[4], bh[4][2];
            {
                int base = ((row_w + ky)*8 + w4)*76 + 3 + kx + xbh*32 + mp*16 + r4;
                ah[0]=Ah[base]; ah[1]=Ah[base+8]; ah[2]=Ah[base+304]; ah[3]=Ah[base+312];
            }
            #pragma unroll
            for (int n=0;n<4;n++){
                int bidx = (tap*8 + w4)*40 + n*8 + r4;
                bh[n][0]=Bh[bidx]; bh[n][1]=Bh[bidx+160];
            }
            #pragma unroll
            for (int n=0;n<4;n++)
                MMA16816(acc[n], ah, bh[n]);
        }
        __syncthreads();
        buf ^= 1;
    }

    float* fb = feat + (size_t)b*FEATB;
    unsigned* oh = gActHi + (size_t)b*NWORD*HW;
    int y = y0 + row_w;
    int xp = xbh*32 + mp*16 + r4;
    #pragma unroll
    for (int n=0;n<4;n++){
        int chl = ng*32 + n*8 + 2*w4;
        if (chl < cout){
            float b0 = bias[chl], b1 = bias[chl+1];
            #pragma unroll
            for (int h=0; h<2; h++){
                float v0 = lrelu(acc[n][2*h+0] + b0);
                float v1 = lrelu(acc[n][2*h+1] + b1);
                int xx = xp + h*8;
                size_t o = (size_t)(obase_ch + chl)*HW + y*W4 + xx;
                fb[o]      = v0;
                fb[o + HW] = v1;
                oh[(size_t)((obase_ch + chl) >> 1)*HW + y*W4 + xx] = packh2(v0, v1);
            }
        }
    }
}

// ============ layer 6: split partials + reduce
__global__ void __launch_bounds__(256) k_conv6p(const float* __restrict__ inb,
    const float* __restrict__ W)
{
    const int blk = blockIdx.x;
    const int sp = blockIdx.y;
    const int b = blk / 7, rt = blk % 7;
    const int y0 = rt*4;
    const int cs = (FEATC*sp)/4, ce = (FEATC*(sp+1))/4;
    const int tid = threadIdx.x;
    const int x = tid & 63, yl = tid >> 6;
    __shared__ float s6[4][6][66];
    __shared__ float sw0[4][9], sw1[4][9];
    const float* ibase = inb + (size_t)b*FEATB;
    float a0 = 0.f, a1 = 0.f;
    for (int c0=cs; c0<ce; c0+=4){
        __syncthreads();
        for (int i=tid; i<4*6*66; i+=256){
            int cc = i/396, r = (i/66)%6, col = i%66;
            int gy = y0 - 1 + r, gx = col - 1, c = c0+cc;
            float v = 0.f;
            if (c < ce && gy>=0 && gy<H4 && gx>=0 && gx<W4) v = ibase[(size_t)c*HW + gy*W4 + gx];
            s6[cc][r][col] = v;
        }
        if (tid < 36){
            int cc = tid/9, k = tid%9, c = c0+cc;
            sw0[cc][k] = (c < ce) ? W[(size_t)c*9 + k] : 0.f;
            sw1[cc][k] = (c < ce) ? W[(size_t)(FEATC + c)*9 + k] : 0.f;
        }
        __syncthreads();
        #pragma unroll
        for (int cc=0;cc<4;cc++)
            #pragma unroll
            for (int dy=0;dy<3;dy++)
                #pragma unroll
                for (int dx=0;dx<3;dx++){
                    float v = s6[cc][yl+dy][x+dx];
                    a0 += v*sw0[cc][dy*3+dx];
                    a1 += v*sw1[cc][dy*3+dx];
                }
    }
    size_t base = ((size_t)(sp*Bsz + b)*2)*HW + (y0+yl)*W4 + x;
    gDF[base]      = a0;
    gDF[base + HW] = a1;
}

__global__ void k_c6red(const float* __restrict__ bias, float* __restrict__ flow_out){
    int idx = blockIdx.x*blockDim.x + threadIdx.x;
    if (idx >= Bsz*2*HW) return;
    int pq = idx % HW;
    int o  = (idx / HW) & 1;
    int b  = idx / (2*HW);
    float s = bias[o];
    for (int sp=0; sp<4; sp++)
        s += gDF[((size_t)(sp*Bsz + b)*2 + o)*HW + pq];
    flow_out[((size_t)b*2 + o)*HW + pq] = lrelu(s);
}

static inline int cdiv(int a, int b){ return (a + b - 1) / b; }

extern "C" void kernel_launch(void* const* d_in, const int* in_sizes, int n_in,
                              void* d_out, int out_size) {
    const float* tenOne   = (const float*)d_in[0];
    const float* tenTwo   = (const float*)d_in[1];
    const float* prev_flow= (const float*)d_in[2];
    const float* prev_feat= (const float*)d_in[3];
    const float* quat     = (const float*)d_in[4];
    const float* K        = (const float*)d_in[5];
    const float* Kinv     = (const float*)d_in[6];
    const float* upflow_w = (const float*)d_in[7];
    const float* upflow_b = (const float*)d_in[8];
    const float* upfeat_w = (const float*)d_in[9];
    const float* upfeat_b = (const float*)d_in[10];
    const float* w1=(const float*)d_in[11]; const float* b1=(const float*)d_in[12];
    const float* w2=(const float*)d_in[13]; const float* b2=(const float*)d_in[14];
    const float* w3=(const float*)d_in[15]; const float* b3=(const float*)d_in[16];
    const float* w4=(const float*)d_in[17]; const float* b4=(const float*)d_in[18];
    const float* w5=(const float*)d_in[19]; const float* b5=(const float*)d_in[20];
    const float* w6=(const float*)d_in[21]; const float* b6=(const float*)d_in[22];

    float* out      = (float*)d_out;
    float* flow_out = out;
    float* feat     = out + (size_t)Bsz*2*HW;

    cudaFuncSetAttribute(k_gemm,  cudaFuncAttributeMaxDynamicSharedMemorySize, SMEM_GEMM);
    cudaFuncSetAttribute(k_gemm2, cudaFuncAttributeMaxDynamicSharedMemorySize, SMEM_GEMM2);

    k_prep<<<16352, 256>>>(quat, K, Kinv, tenOne, prev_flow, upflow_w, upflow_b,
                           prev_feat, upfeat_w, w1, w2, w3, w4, w5, feat);
    k_prep2<<<336, 256>>>(upfeat_b, feat);

    k_warp1<<<dim3(112,12), 256>>>(tenTwo, feat);
    k_warp2<<<dim3(112,12), 256>>>(feat);
    k_corr<<<dim3(7, Bsz), 256>>>(tenOne, feat);

    k_gemm <<<dim3(112,4),256,SMEM_GEMM >>>(b1, feat, 224, 12, 128, 128, 320, 0);
    k_gemm <<<dim3(112,4),256,SMEM_GEMM >>>(b2, feat, 160, 20, 128, 128, 192, 110592);
    k_gemm2<<<dim3(224,3),256,SMEM_GEMM2>>>(b3, feat,  96, 28, 128,  96,  96, 294912);
    k_gemm2<<<dim3(224,2),256,SMEM_GEMM2>>>(b4, feat,  48, 34,  64,  64,  32, 552960);
    k_gemm2<<<dim3(224,1),256,SMEM_GEMM2>>>(b5, feat,  16, 38,  64,  32,   0, 709632);

    k_conv6p<<<dim3(Bsz*7,4), 256>>>(feat, w6);
    k_c6red<<<cdiv(Bsz*2*HW,256), 256>>>(b6, flow_out);
}

// round 17
// speedup vs baseline: 1.1695x; 1.1695x over previous
#include <cuda_runtime.h>
#include <cuda_fp16.h>
#include <cstdint>
#include <cstddef>

#define Bsz 16
#define H4 28
#define W4 64
#define HW (H4*W4)
#define C1 96
#define FEATC 631
#define FEATB (FEATC*HW)
#define FULL_H 448
#define FULL_W 1024
#define NWORD 320
#define NS 8

__device__ float gRv[(size_t)Bsz*2*H4*FULL_W];
__device__ float gW1[(size_t)Bsz*C1*HW];
__device__ float gW2[(size_t)Bsz*C1*HW];
__device__ unsigned gActHi[(size_t)Bsz*NWORD*HW];
__device__ unsigned gWpHi[884736];
__device__ float gDF[(size_t)NS*Bsz*2*HW];

__device__ __forceinline__ float lrelu(float v){ return v >= 0.f ? v : 0.1f*v; }
__device__ __forceinline__ unsigned packh2(float a, float b){
    __half h0 = __float2half_rn(a), h1 = __float2half_rn(b);
    return ((unsigned)__half_as_ushort(h1) << 16) | (unsigned)__half_as_ushort(h0);
}

// ============ fused prep: resizeVf | copyone | deconv_flow | dfeat | wpack×5
__global__ void __launch_bounds__(256) k_prep(
    const float* __restrict__ quat, const float* __restrict__ K, const float* __restrict__ Kinv,
    const float* __restrict__ tenOne,
    const float* __restrict__ prev_flow, const float* __restrict__ upflow_w, const float* __restrict__ upflow_b,
    const float* __restrict__ prev_feat, const float* __restrict__ upfeat_w,
    const float* __restrict__ w1, const float* __restrict__ w2, const float* __restrict__ w3,
    const float* __restrict__ w4, const float* __restrict__ w5,
    float* __restrict__ feat)
{
    __shared__ float sh[1936];
    const int blk = blockIdx.x;
    const int tid = threadIdx.x;

    if (blk < 1792){
        int idx = blk*256 + tid;
        int x = idx % FULL_W;
        int i = (idx / FULL_W) % H4;
        int b = idx / (FULL_W*H4);
        float* M = &sh[1920];
        if (tid == 0){
            float q0=quat[b*4+0], q1=quat[b*4+1], q2=quat[b*4+2], q3=quat[b*4+3];
            float n = sqrtf(q0*q0+q1*q1+q2*q2+q3*q3);
            float w=q0/n, xr=q1/n, yr=q2/n, zr=q3/n;
            float R[9];
            R[0]=1.f-2.f*(yr*yr+zr*zr); R[1]=2.f*(xr*yr-w*zr);      R[2]=2.f*(xr*zr+w*yr);
            R[3]=2.f*(xr*yr+w*zr);      R[4]=1.f-2.f*(xr*xr+zr*zr); R[5]=2.f*(yr*zr-w*xr);
            R[6]=2.f*(xr*zr-w*yr);      R[7]=2.f*(yr*zr+w*xr);      R[8]=1.f-2.f*(xr*xr+yr*yr);
            float T[9];
            for (int ii=0;ii<3;ii++) for (int jj=0;jj<3;jj++){
                float s=0.f; for (int k=0;k<3;k++) s += K[ii*3+k]*R[k*3+jj]; T[ii*3+jj]=s;
            }
            for (int ii=0;ii<3;ii++) for (int jj=0;jj<3;jj++){
                float s=0.f; for (int k=0;k<3;k++) s += T[ii*3+k]*Kinv[k*3+jj]; M[ii*3+jj]=s;
            }
        }
        __syncthreads();
        float M1=M[1],M4=M[4],M7=M[7];
        float fx = (float)x;
        float ux = M[0]*fx + M[2], vx = M[3]*fx + M[5], wxc = M[6]*fx + M[8];
        float pos = 16.0f*i + 7.5f;
        int ys = 16*i - 8;
        int yA = ys < 0 ? 0 : ys;
        int yB = (ys+31 > FULL_H-1) ? (FULL_H-1) : (ys+31);
        float a0=0.f, a1=0.f, ws=0.f;
        float w = wxc + M7*(float)yA;
        float r = 1.0f / w;
        for (int yy=yA; yy<=yB; yy++){
            float fy = (float)yy;
            r = r*(2.0f - w*r);
            float wgt = 1.0f - fabsf(fy - pos) * 0.0625f;
            a0 += wgt * ((ux + M1*fy)*r - fx);
            a1 += wgt * ((vx + M4*fy)*r - fy);
            ws += wgt;
            w += M7;
        }
        float rws = 1.0f / ws;
        size_t o = ((size_t)(b*2)*H4 + i)*FULL_W + x;
        gRv[o]                     = a0*rws;
        gRv[o + (size_t)H4*FULL_W] = a1*rws;
    }
    else if (blk < 12544){
        int idx = (blk-1792)*256 + tid;
        int p = idx % HW;
        int c = (idx / HW) % C1;
        int b = idx / (HW*C1);
        feat[(size_t)b*FEATB + (size_t)(531+c)*HW + p] = tenOne[idx];
    }
    else if (blk < 12768){
        int idx = (blk-12544)*256 + tid;
        int x = idx % W4;
        int y = (idx / W4) % H4;
        int o = (idx / HW) % 2;
        int b = idx / (2*HW);
        float acc = upflow_b[o];
        for (int t=0;t<2;t++){
            int ky = (y & 1) + 2*t;
            int iy = (y + ky - 2) / 2;
            if ((y + ky - 2) < 0 || iy >= 14) continue;
            for (int s=0;s<2;s++){
                int kx = (x & 1) + 2*s;
                int ix = (x + kx - 2) / 2;
                if ((x + kx - 2) < 0 || ix >= 32) continue;
                for (int c=0;c<2;c++)
                    acc += prev_flow[((b*2 + c)*14 + iy)*32 + ix] * upflow_w[((c*2 + o)*4 + (3-ky))*4 + (3-kx)];
            }
        }
        feat[(size_t)b*FEATB + (size_t)(627+o)*HW + y*W4 + x] = acc;
    }
    else if (blk < 12896){
        int local = blk - 12768;
        int b = local & 15, sp = local >> 4;
        int cs = (663*sp)/NS, ce = (663*(sp+1))/NS;
        int x = tid & 63;
        int ybase = tid >> 6;
        float* sd  = sh;
        float* swt = sh + 1792;
        int ixs[2], wbs[2], nkx=0;
        for (int t=0;t<2;t++){
            int kx=(x&1)+2*t, num=x+kx-2, ix=num/2;
            if (num>=0 && ix<32){ ixs[nkx]=ix; wbs[nkx]=3-kx; nkx++; }
        }
        int p = ybase & 1;
        int wrow[2] = {3-p, 1-p};
        int iyk[7][2]; unsigned vmask[7];
        #pragma unroll
        for (int k=0;k<7;k++){
            int y = ybase + 4*k;
            vmask[k]=0;
            #pragma unroll
            for (int t=0;t<2;t++){
                int ky=(y&1)+2*t, num=y+ky-2, iy=num/2;
                if (num>=0 && iy<14) vmask[k] |= (1u<<t);
                iyk[k][t] = (iy<0)?0:((iy>13)?13:iy);
            }
        }
        float acc0[7], acc1[7];
        #pragma unroll
        for (int k=0;k<7;k++){ acc0[k]=0.f; acc1[k]=0.f; }

        for (int c=cs; c<ce; c+=4){
            __syncthreads();
            for (int i=tid; i<4*448; i+=256){
                int k = i / 448, j = i % 448;
                sd[k*448+j] = (c+k < ce) ? prev_feat[((size_t)b*663 + c+k)*448 + j] : 0.f;
            }
            if (tid < 128){
                int k = tid >> 5, j = tid & 31;
                swt[k*32+j] = (c+k < ce) ? upfeat_w[(size_t)(c+k)*32 + j] : 0.f;
            }
            __syncthreads();
            #pragma unroll
            for (int cc=0; cc<4; cc++){
                float wr[2][2][2];
                #pragma unroll
                for (int t=0;t<2;t++)
                    for (int j=0;j<2;j++){
                        int wc = (j<nkx)? wbs[j] : 0;
                        wr[0][t][j] = (j<nkx)? swt[cc*32 + wrow[t]*4 + wc]      : 0.f;
                        wr[1][t][j] = (j<nkx)? swt[cc*32 + 16 + wrow[t]*4 + wc] : 0.f;
                    }
                #pragma unroll
                for (int k=0;k<7;k++){
                    #pragma unroll
                    for (int t=0;t<2;t++){
                        if (!(vmask[k]>>t & 1)) continue;
                        const float* row = &sd[cc*448 + iyk[k][t]*32];
                        #pragma unroll
                        for (int j=0;j<2;j++){
                            if (j>=nkx) break;
                            float v = row[ixs[j]];
                            acc0[k] += v*wr[0][t][j];
                            acc1[k] += v*wr[1][t][j];
                        }
                    }
                }
            }
        }
        size_t base = ((size_t)(sp*Bsz + b)*2)*HW;
        #pragma unroll
        for (int k=0;k<7;k++){
            int y = ybase + 4*k;
            gDF[base + y*W4 + x]      = acc0[k];
            gDF[base + HW + y*W4 + x] = acc1[k];
        }
    }
    else {
        int wb = blk - 12896;
        const float* w; int cin, cout, coutp, off, idx;
        if (wb < 432)      { w=w1; cin=183; cout=128; coutp=128; off=0;      idx = wb*256 + tid; }
        else if (wb < 1152){ w=w2; cin=311; cout=128; coutp=128; off=110592; idx = (wb-432)*256 + tid; }
        else if (wb < 2160){ w=w3; cin=439; cout= 96; coutp=128; off=294912; idx = (wb-1152)*256 + tid; }
        else if (wb < 2772){ w=w4; cin=535; cout= 64; coutp= 64; off=552960; idx = (wb-2160)*256 + tid; }
        else               { w=w5; cin=599; cout= 32; coutp= 64; off=709632; idx = (wb-2772)*256 + tid; }
        int n    = idx % coutp;
        int w8   = (idx / coutp) % 8;
        int tap  = (idx / (coutp*8)) % 9;
        int chunk= idx / (coutp*72);
        int c0 = 2*(chunk*8 + w8), c1 = c0 + 1;
        float v0 = (n < cout && c0 < cin) ? w[((size_t)n*cin + c0)*9 + tap] : 0.f;
        float v1 = (n < cout && c1 < cin) ? w[((size_t)n*cin + c1)*9 + tap] : 0.f;
        gWpHi[off + idx] = packh2(v0, v1);
    }
}

// ============ fused prep2: resizeH | dfred
__global__ void __launch_bounds__(256) k_prep2(const float* __restrict__ upfeat_b, float* __restrict__ feat){
    const int blk = blockIdx.x;
    const int tid = threadIdx.x;
    if (blk < 112){
        int idx = blk*256 + tid;
        int j = idx % W4;
        int i = (idx / W4) % H4;
        int b = idx / HW;
        float pos = 16.0f*j + 7.5f;
        int xs = 16*j - 8;
        float a0=0.f, a1=0.f, ws=0.f;
        const float* p0 = &gRv[((size_t)(b*2)*H4 + i)*FULL_W];
        const float* p1 = p0 + (size_t)H4*FULL_W;
        for (int t=0;t<32;t++){
            int xx = xs + t;
            if (xx < 0 || xx >= FULL_W) continue;
            float wgt = 1.0f - fabsf((float)xx - pos) * 0.0625f;
            a0 += wgt * p0[xx];
            a1 += wgt * p1[xx];
            ws += wgt;
        }
        float rws = 1.0f / ws;
        size_t o = (size_t)b*FEATB + (size_t)529*HW + i*W4 + j;
        feat[o]      = (a0*rws)*0.0625f;
        feat[o + HW] = (a1*rws)*0.0625f;
    } else {
        int idx = (blk-112)*256 + tid;
        int pq = idx % HW;
        int o  = (idx / HW) & 1;
        int b  = idx / (2*HW);
        float s = upfeat_b[o];
        for (int sp=0; sp<NS; sp++)
            s += gDF[((size_t)(sp*Bsz + b)*2 + o)*HW + pq];
        feat[(size_t)b*FEATB + (size_t)(629+o)*HW + pq] = s;
    }
}

// ============ bilinear warps (12-way channel-split)
__device__ __forceinline__ void warp_px(const float* __restrict__ srcB, float* __restrict__ dstB,
                                        float fx, float fy, int x, int y, int c0, int c1){
    float xx = (float)x + fx, yy = (float)y + fy;
    float x0 = floorf(xx), y0 = floorf(yy);
    float wx = xx - x0, wy = yy - y0;
    float ys2[2] = { y0, y0 + 1.f };
    float xs2[2] = { x0, x0 + 1.f };
    float wyv[2] = { 1.f - wy, wy };
    float wxv[2] = { 1.f - wx, wx };
    float wgt[4]; int off[4];
    #pragma unroll
    for (int i=0;i<2;i++)
        #pragma unroll
        for (int j=0;j<2;j++){
            bool valid = (ys2[i] >= 0.f) && (ys2[i] <= (float)(H4-1)) && (xs2[j] >= 0.f) && (xs2[j] <= (float)(W4-1));
            float yc = fminf(fmaxf(ys2[i], 0.f), (float)(H4-1));
            float xc = fminf(fmaxf(xs2[j], 0.f), (float)(W4-1));
            off[i*2+j] = (int)yc * W4 + (int)xc;
            wgt[i*2+j] = valid ? (wyv[i]*wxv[j]) : 0.f;
        }
    int obase = y*W4 + x;
    #pragma unroll
    for (int c=c0;c<c1;c++){
        const float* s = srcB + (size_t)c*HW;
        dstB[(size_t)c*HW + obase] = wgt[0]*s[off[0]] + wgt[1]*s[off[1]] + wgt[2]*s[off[2]] + wgt[3]*s[off[3]];
    }
}

__global__ void k_warp1(const float* __restrict__ tenTwo, const float* __restrict__ feat){
    int idx = blockIdx.x*blockDim.x + threadIdx.x;
    if (idx >= Bsz*HW) return;
    int cg = blockIdx.y;
    int x = idx % W4, y = (idx / W4) % H4, b = idx / HW;
    const float* fp = feat + (size_t)b*FEATB + (size_t)529*HW + y*W4 + x;
    warp_px(tenTwo + (size_t)b*C1*HW, gW1 + (size_t)b*C1*HW, fp[0], fp[HW], x, y, cg*8, cg*8+8);
}
__global__ void k_warp2(const float* __restrict__ feat){
    int idx = blockIdx.x*blockDim.x + threadIdx.x;
    if (idx >= Bsz*HW) return;
    int cg = blockIdx.y;
    int x = idx % W4, y = (idx / W4) % H4, b = idx / HW;
    const float* fp = feat + (size_t)b*FEATB + (size_t)627*HW + y*W4 + x;
    warp_px(gW1 + (size_t)b*C1*HW, gW2 + (size_t)b*C1*HW, fp[0]*1.25f, fp[HW]*1.25f, x, y, cg*8, cg*8+8);
}

// ============ correlation + packed fp16 act words 224..263
__global__ void __launch_bounds__(256) k_corr(const float* __restrict__ one, float* __restrict__ feat){
    __shared__ float s1[8][4][64];
    __shared__ float s2[8][12][72];
    int tid = threadIdx.x;
    int tx = tid % 64, tyl = tid / 64;
    int b = blockIdx.y, rt = blockIdx.x;
    int y = rt*4 + tyl;
    float acc[81];
    #pragma unroll
    for (int d=0; d<81; d++) acc[d] = 0.f;
    const float* oneB = one + (size_t)b*C1*HW;
    const float* twoB = gW2 + (size_t)b*C1*HW;
    for (int c0=0; c0<C1; c0+=8){
        __syncthreads();
        for (int i=tid; i<8*4*64; i+=256){
            int c = i / 256; int r = (i / 64) % 4; int xx = i % 64;
            s1[c][r][xx] = oneB[(size_t)(c0+c)*HW + (rt*4+r)*64 + xx];
        }
        for (int i=tid; i<8*12*72; i+=256){
            int c = i / (12*72); int rem = i % (12*72);
            int r = rem / 72; int xx = rem % 72;
            int gy = rt*4 + r - 4, gx = xx - 4;
            float v = 0.f;
            if (gy >= 0 && gy < H4 && gx >= 0 && gx < W4) v = twoB[(size_t)(c0+c)*HW + gy*64 + gx];
            s2[c][r][xx] = v;
        }
        __syncthreads();
        #pragma unroll
        for (int c=0;c<8;c++){
            float f1 = s1[c][tyl][tx];
            #pragma unroll
            for (int dy=0;dy<9;dy++){
                const float* row = &s2[c][tyl+dy][tx];
                #pragma unroll
                for (int dx=0;dx<9;dx++) acc[dy*9+dx] += f1 * row[dx];
            }
        }
    }
    float* fb = feat + (size_t)b*FEATB + (size_t)448*HW + y*64 + tx;
    const float inv = 1.0f/96.0f;
    #pragma unroll
    for (int d=0; d<81; d++){
        acc[d] = lrelu(acc[d]*inv);
        fb[(size_t)d*HW] = acc[d];
    }
    unsigned* oh = gActHi + ((size_t)b*NWORD + 224)*HW + y*64 + tx;
    #pragma unroll
    for (int k=0;k<40;k++)
        oh[(size_t)k*HW] = packh2(acc[2*k], acc[2*k+1]);
}

// ============ fp32 -> packed fp16 (words 264..319)
__global__ void k_cvt(const float* __restrict__ feat, int w0, int nw){
    int idx = blockIdx.x*blockDim.x + threadIdx.x;
    if (idx >= Bsz*nw*HW) return;
    int px = idx % HW;
    int wr = (idx / HW) % nw;
    int b  = idx / (HW*nw);
    int w = w0 + wr;
    int c0 = 2*w, c1 = 2*w+1;
    const float* fb = feat + (size_t)b*FEATB;
    float x0 = (c0 < FEATC) ? fb[(size_t)c0*HW + px] : 0.f;
    float x1 = (c1 < FEATC) ? fb[(size_t)c1*HW + px] : 0.f;
    gActHi[((size_t)b*NWORD + w)*HW + px] = packh2(x0, x1);
}

#define MMA16816(d, a, b) \
    asm volatile("mma.sync.aligned.m16n8k16.row.col.f32.f16.f16.f32 " \
        "{%0,%1,%2,%3}, {%4,%5,%6,%7}, {%8,%9}, {%0,%1,%2,%3};" \
        : "+f"(d[0]), "+f"(d[1]), "+f"(d[2]), "+f"(d[3]) \
        : "r"(a[0]), "r"(a[1]), "r"(a[2]), "r"(a[3]), "r"(b[0]), "r"(b[1]))

__device__ __forceinline__ void cpa16(unsigned dst, const void* src){
    asm volatile("cp.async.ca.shared.global [%0], [%1], 16;" :: "r"(dst), "l"(src));
}

#define ABUF 3648
#define BBUF 2880
#define SMEMW (2*ABUF + 2*BBUF)
#define SMEM_GEMM (SMEMW*4)

__global__ void __launch_bounds__(256,3) k_gemm(const float* __restrict__ bias, float* __restrict__ feat,
    int cs_word, int chunks, int coutp, int cout, int obase_ch, int wp_off)
{
    extern __shared__ unsigned sm[];
    unsigned* sAh = sm;
    unsigned* sBh = sm + 2*ABUF;
    const unsigned sbase = (unsigned)__cvta_generic_to_shared(sm);

    const int tile = blockIdx.x;
    const int ng = blockIdx.y;
    const int b = tile / 7;
    const int y0 = (tile % 7) * 4;
    const int tid = threadIdx.x;
    const int lane = tid & 31, warp = tid >> 5;
    const int row_w = warp >> 1;
    const int xb = (warp & 1) * 32;
    const int r4 = lane >> 2, w4 = lane & 3;

    for (int i=tid; i<SMEMW; i+=256) sm[i] = 0u;
    __syncthreads();

    const unsigned* gh = gActHi + (size_t)b*NWORD*HW;

    float acc[2][4][4];
    #pragma unroll
    for (int m=0;m<2;m++)
        #pragma unroll
        for (int n=0;n<4;n++){ acc[m][n][0]=0.f; acc[m][n][1]=0.f; acc[m][n][2]=0.f; acc[m][n][3]=0.f; }

    auto load_chunk = [&](int ch, int bf){
        int cw0 = cs_word + ch*8;
        #pragma unroll
        for (int it=0; it<3; it++){
            int i = it*256 + tid;
            int q = i & 15;
            int j = i >> 4;
            int r = j % 6;
            int w = j / 6;
            int gy = y0 - 1 + r;
            if (gy >= 0 && gy < H4){
                const unsigned* src = gh + (size_t)(cw0+w)*HW + gy*W4 + q*4;
                unsigned dst = sbase + (bf*ABUF + (w*6+r)*76 + 4 + q*4)*4;
                cpa16(dst, src);
            }
        }
        for (int i=tid; i<576; i+=256){
            int q = i & 7;
            int tw = i >> 3;
            const unsigned* src = gWpHi + wp_off + (size_t)(ch*72 + tw)*coutp + ng*32 + q*4;
            unsigned dst = sbase + (2*ABUF + bf*BBUF + tw*40 + q*4)*4;
            cpa16(dst, src);
        }
    };

    load_chunk(0, 0);
    asm volatile("cp.async.commit_group;");
    int buf = 0;
    for (int ch=0; ch<chunks; ch++){
        if (ch+1 < chunks) load_chunk(ch+1, buf^1);
        asm volatile("cp.async.commit_group;");
        asm volatile("cp.async.wait_group 1;");
        __syncthreads();

        const unsigned* Ah = sAh + buf*ABUF;
        const unsigned* Bh = sBh + buf*BBUF;
        #pragma unroll
        for (int tap=0; tap<9; tap++){
            int ky = tap/3, kx = tap%3;
            unsigned ah[2][4], bh[4][2];
            #pragma unroll
            for (int m=0;m<2;m++){
                int base = (w4*6 + row_w + ky)*76 + 3 + kx + xb + m*16 + r4;
                ah[m][0]=Ah[base]; ah[m][1]=Ah[base+8]; ah[m][2]=Ah[base+1824]; ah[m][3]=Ah[base+1832];
            }
            #pragma unroll
            for (int n=0;n<4;n++){
                int bidx = (tap*8 + w4)*40 + n*8 + r4;
                bh[n][0]=Bh[bidx]; bh[n][1]=Bh[bidx+160];
            }
            #pragma unroll
            for (int m=0;m<2;m++)
                #pragma unroll
                for (int n=0;n<4;n++)
                    MMA16816(acc[m][n], ah[m], bh[n]);
        }
        __syncthreads();
        buf ^= 1;
    }

    float* fb = feat + (size_t)b*FEATB;
    unsigned* oh = gActHi + (size_t)b*NWORD*HW;
    int y = y0 + row_w;
    #pragma unroll
    for (int m=0;m<2;m++){
        int xp = xb + m*16 + r4;
        #pragma unroll
        for (int n=0;n<4;n++){
            int chl = ng*32 + n*8 + 2*w4;
            if (chl < cout){
                float b0 = bias[chl], b1 = bias[chl+1];
                #pragma unroll
                for (int h=0; h<2; h++){
                    float v0 = lrelu(acc[m][n][2*h+0] + b0);
                    float v1 = lrelu(acc[m][n][2*h+1] + b1);
                    int xx = xp + h*8;
                    size_t o = (size_t)(obase_ch + chl)*HW + y*W4 + xx;
                    fb[o]      = v0;
                    fb[o + HW] = v1;
                    oh[(size_t)((obase_ch + chl) >> 1)*HW + y*W4 + xx] = packh2(v0, v1);
                }
            }
        }
    }
}

// ============ layer 6: 8-way split partials + reduce
__global__ void __launch_bounds__(256) k_conv6p(const float* __restrict__ inb,
    const float* __restrict__ W)
{
    const int blk = blockIdx.x;
    const int sp = blockIdx.y;
    const int b = blk / 7, rt = blk % 7;
    const int y0 = rt*4;
    const int cs = (FEATC*sp)/8, ce = (FEATC*(sp+1))/8;
    const int tid = threadIdx.x;
    const int x = tid & 63, yl = tid >> 6;
    __shared__ float s6[4][6][66];
    __shared__ float sw0[4][9], sw1[4][9];
    const float* ibase = inb + (size_t)b*FEATB;
    float a0 = 0.f, a1 = 0.f;
    for (int c0=cs; c0<ce; c0+=4){
        __syncthreads();
        for (int i=tid; i<4*6*66; i+=256){
            int cc = i/396, r = (i/66)%6, col = i%66;
            int gy = y0 - 1 + r, gx = col - 1, c = c0+cc;
            float v = 0.f;
            if (c < ce && gy>=0 && gy<H4 && gx>=0 && gx<W4) v = ibase[(size_t)c*HW + gy*W4 + gx];
            s6[cc][r][col] = v;
        }
        if (tid < 36){
            int cc = tid/9, k = tid%9, c = c0+cc;
            sw0[cc][k] = (c < ce) ? W[(size_t)c*9 + k] : 0.f;
            sw1[cc][k] = (c < ce) ? W[(size_t)(FEATC + c)*9 + k] : 0.f;
        }
        __syncthreads();
        #pragma unroll
        for (int cc=0;cc<4;cc++)
            #pragma unroll
            for (int dy=0;dy<3;dy++)
                #pragma unroll
                for (int dx=0;dx<3;dx++){
                    float v = s6[cc][yl+dy][x+dx];
                    a0 += v*sw0[cc][dy*3+dx];
                    a1 += v*sw1[cc][dy*3+dx];
                }
    }
    size_t base = ((size_t)(sp*Bsz + b)*2)*HW + (y0+yl)*W4 + x;
    gDF[base]      = a0;
    gDF[base + HW] = a1;
}

__global__ void k_c6red(const float* __restrict__ bias, float* __restrict__ flow_out){
    int idx = blockIdx.x*blockDim.x + threadIdx.x;
    if (idx >= Bsz*2*HW) return;
    int pq = idx % HW;
    int o  = (idx / HW) & 1;
    int b  = idx / (2*HW);
    float s = bias[o];
    for (int sp=0; sp<8; sp++)
        s += gDF[((size_t)(sp*Bsz + b)*2 + o)*HW + pq];
    flow_out[((size_t)b*2 + o)*HW + pq] = lrelu(s);
}

static inline int cdiv(int a, int b){ return (a + b - 1) / b; }

extern "C" void kernel_launch(void* const* d_in, const int* in_sizes, int n_in,
                              void* d_out, int out_size) {
    const float* tenOne   = (const float*)d_in[0];
    const float* tenTwo   = (const float*)d_in[1];
    const float* prev_flow= (const float*)d_in[2];
    const float* prev_feat= (const float*)d_in[3];
    const float* quat     = (const float*)d_in[4];
    const float* K        = (const float*)d_in[5];
    const float* Kinv     = (const float*)d_in[6];
    const float* upflow_w = (const float*)d_in[7];
    const float* upflow_b = (const float*)d_in[8];
    const float* upfeat_w = (const float*)d_in[9];
    const float* upfeat_b = (const float*)d_in[10];
    const float* w1=(const float*)d_in[11]; const float* b1=(const float*)d_in[12];
    const float* w2=(const float*)d_in[13]; const float* b2=(const float*)d_in[14];
    const float* w3=(const float*)d_in[15]; const float* b3=(const float*)d_in[16];
    const float* w4=(const float*)d_in[17]; const float* b4=(const float*)d_in[18];
    const float* w5=(const float*)d_in[19]; const float* b5=(const float*)d_in[20];
    const float* w6=(const float*)d_in[21]; const float* b6=(const float*)d_in[22];

    float* out      = (float*)d_out;
    float* flow_out = out;
    float* feat     = out + (size_t)Bsz*2*HW;

    cudaFuncSetAttribute(k_gemm, cudaFuncAttributeMaxDynamicSharedMemorySize, SMEM_GEMM);

    k_prep<<<16352, 256>>>(quat, K, Kinv, tenOne, prev_flow, upflow_w, upflow_b,
                           prev_feat, upfeat_w, w1, w2, w3, w4, w5, feat);
    k_prep2<<<336, 256>>>(upfeat_b, feat);

    k_warp1<<<dim3(112,12), 256>>>(tenTwo, feat);
    k_warp2<<<dim3(112,12), 256>>>(feat);
    k_corr<<<dim3(7, Bsz), 256>>>(tenOne, feat);

    k_cvt<<<cdiv(Bsz*56*HW,256),256>>>(feat, 264, 56);

    k_gemm<<<dim3(112,4),256,SMEM_GEMM>>>(b1, feat, 224, 12, 128, 128, 320, 0);
    k_gemm<<<dim3(112,4),256,SMEM_GEMM>>>(b2, feat, 160, 20, 128, 128, 192, 110592);
    k_gemm<<<dim3(112,3),256,SMEM_GEMM>>>(b3, feat,  96, 28, 128,  96,  96, 294912);
    k_gemm<<<dim3(112,2),256,SMEM_GEMM>>>(b4, feat,  48, 34,  64,  64,  32, 552960);
    k_gemm<<<dim3(112,1),256,SMEM_GEMM>>>(b5, feat,  16, 38,  64,  32,   0, 709632);

    k_conv6p<<<dim3(Bsz*7,8), 256>>>(feat, w6);
    k_c6red<<<cdiv(Bsz*2*HW,256), 256>>>(b6, flow_out);
}